// round 9
// baseline (speedup 1.0000x reference)
#include <cuda_runtime.h>
#include <math.h>

#define TSEQ   1024
#define NBATCH 64
#define HID    512
#define G3     1536
#define INFEAT 256
#define MROWS  (TSEQ * NBATCH)   // 65536
#define NCTA   128

// packed f32x2 FMA
#define FMA2(d, a, b, c) \
    asm("fma.rn.f32x2 %0, %1, %2, %3;" : "=l"(d) : "l"(a), "l"(b), "l"(c))

__device__ __forceinline__ float2 u2f2(unsigned long long u) {
    float2 f;
    asm("mov.b64 {%0, %1}, %2;" : "=f"(f.x), "=f"(f.y) : "l"(u));
    return f;
}

// ---------------- scratch (device globals; no allocation) ----------------
__device__ float g_xg[(size_t)MROWS * G3];   // [t*64+b][1536] gate preacts
__device__ float g_y0[(size_t)MROWS * HID];  // [t*64+b][512]  tanh(h) of layer 0
__device__ float g_h[3][HID * NBATCH];       // k-major [buf][k][b]; buf2 = zero
// tree barrier state, one per batch group; all counters return to 0 each step
__device__ unsigned g_gcnt[2 * 8 * 32];      // group counters, 128B stride
__device__ unsigned g_rcnt[2 * 32];          // root counters,  128B stride
__device__ unsigned g_genB[2 * 32];          // generations (monotonic)

// ---------------- input projection GEMM: g_xg = A @ W + bias ----------------
__global__ void __launch_bounds__(256) proj_kernel(
    const float* __restrict__ Aext, const float* __restrict__ W,
    const float* __restrict__ bias,
    int K, long sB, long sT)
{
    const int N = G3;
    const float* A = Aext ? Aext : g_y0;

    __shared__ __align__(16) float As2[16][260];  // duplicated pairs: [k][2*row]
    __shared__ __align__(16) float Bs[16][64];    // [k][col]

    int tid  = threadIdx.x;
    int row0 = blockIdx.y * 128;
    int col0 = blockIdx.x * 64;
    int tx = tid & 15, ty = tid >> 4;

    int ar  = row0 + (tid >> 1);
    const float* arow = A + (long)(ar & 63) * sB + (long)(ar >> 6) * sT;
    int akc = (tid & 1) * 8;
    int r2  = (tid >> 1) * 2;

    int bkr = tid >> 4;
    int bc  = (tid & 15) * 4;
    const float* bptr = W + (long)bkr * N + col0 + bc;

    unsigned long long acc[8][2];
#pragma unroll
    for (int i = 0; i < 8; ++i) { acc[i][0] = 0ull; acc[i][1] = 0ull; }

    for (int k0 = 0; k0 < K; k0 += 16) {
        float4 a0 = *(const float4*)(arow + k0 + akc);
        float4 a1 = *(const float4*)(arow + k0 + akc + 4);
        float4 bb = *(const float4*)(bptr + (long)k0 * N);

        *(float2*)&As2[akc + 0][r2] = make_float2(a0.x, a0.x);
        *(float2*)&As2[akc + 1][r2] = make_float2(a0.y, a0.y);
        *(float2*)&As2[akc + 2][r2] = make_float2(a0.z, a0.z);
        *(float2*)&As2[akc + 3][r2] = make_float2(a0.w, a0.w);
        *(float2*)&As2[akc + 4][r2] = make_float2(a1.x, a1.x);
        *(float2*)&As2[akc + 5][r2] = make_float2(a1.y, a1.y);
        *(float2*)&As2[akc + 6][r2] = make_float2(a1.z, a1.z);
        *(float2*)&As2[akc + 7][r2] = make_float2(a1.w, a1.w);
        *(float4*)&Bs[bkr][bc] = bb;
        __syncthreads();

#pragma unroll
        for (int kk = 0; kk < 16; ++kk) {
            ulonglong2 b01 = *(const ulonglong2*)&Bs[kk][tx * 4];
            ulonglong2 a01 = *(const ulonglong2*)&As2[kk][ty * 16];
            ulonglong2 a23 = *(const ulonglong2*)&As2[kk][ty * 16 + 4];
            ulonglong2 a45 = *(const ulonglong2*)&As2[kk][ty * 16 + 8];
            ulonglong2 a67 = *(const ulonglong2*)&As2[kk][ty * 16 + 12];
            unsigned long long ad[8] = {a01.x, a01.y, a23.x, a23.y,
                                        a45.x, a45.y, a67.x, a67.y};
#pragma unroll
            for (int i = 0; i < 8; ++i) {
                FMA2(acc[i][0], ad[i], b01.x, acc[i][0]);
                FMA2(acc[i][1], ad[i], b01.y, acc[i][1]);
            }
        }
        __syncthreads();
    }

    float4 bia = *(const float4*)(bias + col0 + tx * 4);
#pragma unroll
    for (int i = 0; i < 8; ++i) {
        long m = row0 + ty * 8 + i;
        float2 f01 = u2f2(acc[i][0]);
        float2 f23 = u2f2(acc[i][1]);
        float4 v;
        v.x = f01.x + bia.x;
        v.y = f01.y + bia.y;
        v.z = f23.x + bia.z;
        v.w = f23.y + bia.w;
        *(float4*)(g_xg + m * G3 + col0 + tx * 4) = v;
    }
}

// ---------------- persistent GRU recurrence ----------------
// 128 CTAs x 256 threads. CTA (bgrp, hcgrp): batch rows [bgrp*32,+32),
// hidden cols [hcgrp*8,+8). h read straight from L2 in the GEMM loop.
// Barrier: per-bgrp (64 CTAs), two-level tree (8 groups x 8 CTAs) to kill
// single-address atomic serialization.
__global__ void __launch_bounds__(256, 1) gru_rec_kernel(
    const float* __restrict__ Wh, const float* __restrict__ bhn,
    int write_y, float* __restrict__ cout)
{
    const int NB = 32, NG = 24;
    extern __shared__ __align__(16) float sh[];
    float* ws  = sh;                 // [512][24]  48 KB
    float* red = ws + 512 * NG;      // [8][32][26] 26 KB
    float* xgs = red + 8 * 32 * 26;  // [32][25]   2.5 KB

    int tid  = threadIdx.x;
    int warp = tid >> 5, lane = tid & 31;
    int cta  = blockIdx.x;
    int bgrp = cta & 1;
    int hc0  = (cta >> 1) * 8;
    int b0   = bgrp * NB;

    int wid8 = cta >> 1;             // 0..63 within bgrp
    int grp  = wid8 >> 3;            // 0..7
    unsigned* gcnt = &g_gcnt[(bgrp * 8 + grp) * 32];
    unsigned* rcnt = &g_rcnt[bgrp * 32];
    unsigned* genp = &g_genB[bgrp * 32];

    // load W_h slice into SMEM (once)
    for (int f = tid; f < 512 * NG; f += 256) {
        int k = f / NG, j = f - k * NG;
        int gc = (j >> 3) * HID + hc0 + (j & 7);
        ws[f] = Wh[(long)k * G3 + gc];
    }

    // gen only advances after all bgrp CTAs arrive at step-0 barrier -> safe
    unsigned base = *((volatile unsigned*)genp);

    int eci = tid & 7;
    int eb  = tid >> 3;
    int ehc = hc0 + eci;
    float bhn_r = bhn[ehc];

    // xg prefetch registers (warps 0-2: grp = warp, b = lane)
    float4 xv0, xv1;
    const float* xg_base = 0;
    if (tid < 96) {
        int b = tid & 31, gg = tid >> 5;
        xg_base = g_xg + (long)(b0 + b) * G3 + gg * HID + hc0;
        const float* p = xg_base;                     // t = 0
        xv0 = ((const float4*)p)[0];
        xv1 = ((const float4*)p)[1];
    }

    for (int t = 0; t < TSEQ; ++t) {
        int nxt = (t & 1) ^ 1;
        // t==0 reads the never-written zero buffer (branchless, stale-safe)
        const float* hbuf = (t == 0) ? g_h[2] : g_h[t & 1];

        // early: previous h for the gate update (latency hidden under GEMM)
        float hprev = __ldcg(&hbuf[ehc * NBATCH + b0 + eb]);

        // store prefetched xg tile [32 b][24 gate cols]
        if (tid < 96) {
            int b = tid & 31, gg = tid >> 5;
            float* q = xgs + b * 25 + gg * 8;
            q[0] = xv0.x; q[1] = xv0.y; q[2] = xv0.z; q[3] = xv0.w;
            q[4] = xv1.x; q[5] = xv1.y; q[6] = xv1.z; q[7] = xv1.w;
        }

        // partial GEMM: warp w covers k in [w*64, w*64+64), h straight from L2
        unsigned long long acc[12];
#pragma unroll
        for (int j = 0; j < 12; ++j) acc[j] = 0ull;
        int kbase = warp << 6;
        const float* hp = hbuf + (kbase << 6) + b0 + lane;   // + k*64
        const ulonglong2* wp = (const ulonglong2*)(ws + kbase * NG);
#pragma unroll 8
        for (int kk = 0; kk < 64; ++kk) {
            float hv = __ldcg(hp); hp += NBATCH;
            unsigned long long hd;
            asm("mov.b64 %0, {%1, %1};" : "=l"(hd) : "r"(__float_as_int(hv)));
            ulonglong2 w0 = wp[0], w1 = wp[1], w2 = wp[2];
            FMA2(acc[0],  hd, w0.x, acc[0]);
            FMA2(acc[1],  hd, w0.y, acc[1]);
            FMA2(acc[2],  hd, w1.x, acc[2]);
            FMA2(acc[3],  hd, w1.y, acc[3]);
            FMA2(acc[4],  hd, w2.x, acc[4]);
            FMA2(acc[5],  hd, w2.y, acc[5]);
            ulonglong2 w3 = wp[3], w4 = wp[4], w5 = wp[5];
            FMA2(acc[6],  hd, w3.x, acc[6]);
            FMA2(acc[7],  hd, w3.y, acc[7]);
            FMA2(acc[8],  hd, w4.x, acc[8]);
            FMA2(acc[9],  hd, w4.y, acc[9]);
            FMA2(acc[10], hd, w5.x, acc[10]);
            FMA2(acc[11], hd, w5.y, acc[11]);
            wp += 6;   // row stride = 24 floats = 6 ulonglong2
        }
        {
            unsigned long long* rp =
                (unsigned long long*)(red + (warp * NB + lane) * 26);
#pragma unroll
            for (int j = 0; j < 12; ++j) rp[j] = acc[j];
        }
        __syncthreads();   // red + xgs visible

        // reduce 8 warps + gate math
        float hr = 0.f, hz = 0.f, hnv = 0.f;
#pragma unroll
        for (int w = 0; w < 8; ++w) {
            const float* pr = red + (w * NB + eb) * 26;
            hr  += pr[eci];
            hz  += pr[8 + eci];
            hnv += pr[16 + eci];
        }
        float xr = xgs[eb * 25 + eci];
        float xz = xgs[eb * 25 + 8 + eci];
        float xn = xgs[eb * 25 + 16 + eci];

        float rg = 1.f / (1.f + __expf(-(xr + hr)));
        float zg = 1.f / (1.f + __expf(-(xz + hz)));
        float ng = tanhf(xn + rg * (hnv + bhn_r));
        float hnew = (1.f - zg) * ng + zg * hprev;

        g_h[nxt][ehc * NBATCH + b0 + eb] = hnew;
        if (write_y)
            g_y0[((long)t * NBATCH + b0 + eb) * HID + ehc] = tanhf(hnew);
        if (t == TSEQ - 1)
            cout[(b0 + eb) * HID + ehc] = hnew;

        __syncthreads();   // all CTA writes issued before tid0's release

        unsigned target = base + (unsigned)t + 1u;

        // arrive: two-level tree (8-way serialization per level, not 128)
        if (tid == 0) {
            unsigned old;
            asm volatile("atom.acq_rel.gpu.global.add.u32 %0, [%1], %2;"
                         : "=r"(old) : "l"(gcnt), "r"(1u) : "memory");
            if (old == 7u) {
                asm volatile("st.global.u32 [%0], %1;"
                             :: "l"(gcnt), "r"(0u) : "memory");
                unsigned old2;
                asm volatile("atom.acq_rel.gpu.global.add.u32 %0, [%1], %2;"
                             : "=r"(old2) : "l"(rcnt), "r"(1u) : "memory");
                if (old2 == 7u) {
                    asm volatile("st.global.u32 [%0], %1;"
                                 :: "l"(rcnt), "r"(0u) : "memory");
                    asm volatile("st.release.gpu.global.u32 [%0], %1;"
                                 :: "l"(genp), "r"(target) : "memory");
                }
            }
        }

        // overlap: prefetch xg for t+1 while the barrier completes
        if (tid < 96 && t + 1 < TSEQ) {
            const float* p = xg_base + (long)(t + 1) * NBATCH * G3;
            xv0 = ((const float4*)p)[0];
            xv1 = ((const float4*)p)[1];
        }

        // detect: tid0 acquire-polls own bgrp's gen, block barrier fans out
        if (tid == 0) {
            unsigned v;
            do {
                asm volatile("ld.acquire.gpu.global.u32 %0, [%1];"
                             : "=r"(v) : "l"(genp));
            } while ((int)(v - target) < 0);
        }
        __syncthreads();
    }
}

// ---------------- dense head: out = tanh(tanh(c1) @ W_out + b_out) ----------------
__global__ void __launch_bounds__(512) dense_kernel(
    const float* __restrict__ Wout, const float* __restrict__ bout,
    float* __restrict__ out)
{
    __shared__ float tsh[HID];
    int b = blockIdx.x;
    int j = threadIdx.x;
    tsh[j] = tanhf(g_h[0][j * NBATCH + b]);   // final h of layer 1 (k-major)
    __syncthreads();
    float s = bout[j];
#pragma unroll 8
    for (int k = 0; k < HID; ++k)
        s = fmaf(tsh[k], Wout[(long)k * 512 + j], s);
    out[b * 512 + j] = tanhf(s);
}

// ---------------- launch ----------------
extern "C" void kernel_launch(void* const* d_in, const int* in_sizes, int n_in,
                              void* d_out, int out_size)
{
    const float* x     = (const float*)d_in[0];
    const float* W_i0  = (const float*)d_in[1];
    const float* b_i0  = (const float*)d_in[2];
    const float* W_h0  = (const float*)d_in[3];
    const float* b_hn0 = (const float*)d_in[4];
    const float* W_i1  = (const float*)d_in[5];
    const float* b_i1  = (const float*)d_in[6];
    const float* W_h1  = (const float*)d_in[7];
    const float* b_hn1 = (const float*)d_in[8];
    const float* W_out = (const float*)d_in[9];
    const float* b_out = (const float*)d_in[10];

    float* out = (float*)d_out;
    float* c0  = out + 64 * 512;
    float* c1  = out + 2 * 64 * 512;

    size_t rec_smem = (size_t)(512 * 24 + 8 * 32 * 26 + 32 * 25) * sizeof(float);
    cudaFuncSetAttribute(gru_rec_kernel,
                         cudaFuncAttributeMaxDynamicSharedMemorySize, (int)rec_smem);

    dim3 pgrid(G3 / 64, MROWS / 128);

    // layer 0
    proj_kernel<<<pgrid, 256>>>(x, W_i0, b_i0, INFEAT, (long)1024 * 256, (long)256);
    gru_rec_kernel<<<NCTA, 256, rec_smem>>>(W_h0, b_hn0, 1, c0);
    // layer 1
    proj_kernel<<<pgrid, 256>>>(nullptr, W_i1, b_i1, HID, (long)512, (long)64 * 512);
    gru_rec_kernel<<<NCTA, 256, rec_smem>>>(W_h1, b_hn1, 0, c1);
    // head
    dense_kernel<<<64, 512>>>(W_out, b_out, out);
}

// round 10
// speedup vs baseline: 1.1313x; 1.1313x over previous
#include <cuda_runtime.h>
#include <math.h>

#define TSEQ   1024
#define NSTEP  (TSEQ + 2)
#define NBATCH 64
#define HID    512
#define G3     1536
#define INFEAT 256
#define MROWS  (TSEQ * NBATCH)   // 65536
#define NCTA   128

// packed f32x2 FMA
#define FMA2(d, a, b, c) \
    asm("fma.rn.f32x2 %0, %1, %2, %3;" : "=l"(d) : "l"(a), "l"(b), "l"(c))

__device__ __forceinline__ float2 u2f2(unsigned long long u) {
    float2 f;
    asm("mov.b64 {%0, %1}, %2;" : "=f"(f.x), "=f"(f.y) : "l"(u));
    return f;
}

// ---------------- scratch (device globals; no allocation) ----------------
__device__ float g_xg[(size_t)MROWS * G3];    // layer0 gate preacts (proj0)
__device__ float g_h0[3][HID * NBATCH];       // layer0 h ring (k-major); [2]=zero
__device__ float g_h1[3][HID * NBATCH];       // layer1 h ring; [2]=zero
__device__ float g_y0r[2][HID * NBATCH];      // y0 ring (k-major)
__device__ float g_xg1r[2][NBATCH * G3];      // xg1 ring, row-major [b][1536]
__device__ unsigned g_cnt;                    // barrier count (returns to 0)
__device__ unsigned g_gen;                    // generation (monotonic)

// ---------------- input projection GEMM (layer 0 only) ----------------
__global__ void __launch_bounds__(256) proj_kernel(
    const float* __restrict__ A, const float* __restrict__ W,
    const float* __restrict__ bias, int K, long sB, long sT)
{
    const int N = G3;
    __shared__ __align__(16) float As2[16][260];
    __shared__ __align__(16) float Bs[16][64];

    int tid  = threadIdx.x;
    int row0 = blockIdx.y * 128;
    int col0 = blockIdx.x * 64;
    int tx = tid & 15, ty = tid >> 4;

    int ar  = row0 + (tid >> 1);
    const float* arow = A + (long)(ar & 63) * sB + (long)(ar >> 6) * sT;
    int akc = (tid & 1) * 8;
    int r2  = (tid >> 1) * 2;

    int bkr = tid >> 4;
    int bc  = (tid & 15) * 4;
    const float* bptr = W + (long)bkr * N + col0 + bc;

    unsigned long long acc[8][2];
#pragma unroll
    for (int i = 0; i < 8; ++i) { acc[i][0] = 0ull; acc[i][1] = 0ull; }

    for (int k0 = 0; k0 < K; k0 += 16) {
        float4 a0 = *(const float4*)(arow + k0 + akc);
        float4 a1 = *(const float4*)(arow + k0 + akc + 4);
        float4 bb = *(const float4*)(bptr + (long)k0 * N);

        *(float2*)&As2[akc + 0][r2] = make_float2(a0.x, a0.x);
        *(float2*)&As2[akc + 1][r2] = make_float2(a0.y, a0.y);
        *(float2*)&As2[akc + 2][r2] = make_float2(a0.z, a0.z);
        *(float2*)&As2[akc + 3][r2] = make_float2(a0.w, a0.w);
        *(float2*)&As2[akc + 4][r2] = make_float2(a1.x, a1.x);
        *(float2*)&As2[akc + 5][r2] = make_float2(a1.y, a1.y);
        *(float2*)&As2[akc + 6][r2] = make_float2(a1.z, a1.z);
        *(float2*)&As2[akc + 7][r2] = make_float2(a1.w, a1.w);
        *(float4*)&Bs[bkr][bc] = bb;
        __syncthreads();

#pragma unroll
        for (int kk = 0; kk < 16; ++kk) {
            ulonglong2 b01 = *(const ulonglong2*)&Bs[kk][tx * 4];
            ulonglong2 a01 = *(const ulonglong2*)&As2[kk][ty * 16];
            ulonglong2 a23 = *(const ulonglong2*)&As2[kk][ty * 16 + 4];
            ulonglong2 a45 = *(const ulonglong2*)&As2[kk][ty * 16 + 8];
            ulonglong2 a67 = *(const ulonglong2*)&As2[kk][ty * 16 + 12];
            unsigned long long ad[8] = {a01.x, a01.y, a23.x, a23.y,
                                        a45.x, a45.y, a67.x, a67.y};
#pragma unroll
            for (int i = 0; i < 8; ++i) {
                FMA2(acc[i][0], ad[i], b01.x, acc[i][0]);
                FMA2(acc[i][1], ad[i], b01.y, acc[i][1]);
            }
        }
        __syncthreads();
    }

    float4 bia = *(const float4*)(bias + col0 + tx * 4);
#pragma unroll
    for (int i = 0; i < 8; ++i) {
        long m = row0 + ty * 8 + i;
        float2 f01 = u2f2(acc[i][0]);
        float2 f23 = u2f2(acc[i][1]);
        float4 v;
        v.x = f01.x + bia.x;
        v.y = f01.y + bia.y;
        v.z = f23.x + bia.z;
        v.w = f23.y + bia.w;
        *(float4*)(g_xg + m * G3 + col0 + tx * 4) = v;
    }
}

// ---------------- shared per-task GEMM body ----------------
// src: k-major [512][64] in global; wsl: SMEM [512][24]; red: [8][32][26]
__device__ __forceinline__ void task_gemm(
    const float* __restrict__ src, const float* __restrict__ wsl,
    float* __restrict__ red, int warp, int lane, int b0)
{
    unsigned long long acc[12];
#pragma unroll
    for (int j = 0; j < 12; ++j) acc[j] = 0ull;
    int kbase = warp << 6;
    const float* hp = src + kbase * NBATCH + b0 + lane;
    const ulonglong2* wp = (const ulonglong2*)(wsl + kbase * 24);
#pragma unroll 8
    for (int kk = 0; kk < 64; ++kk) {
        float hv = __ldcg(hp); hp += NBATCH;
        unsigned long long hd;
        asm("mov.b64 %0, {%1, %1};" : "=l"(hd) : "r"(__float_as_int(hv)));
        ulonglong2 w0 = wp[0], w1 = wp[1], w2 = wp[2];
        FMA2(acc[0],  hd, w0.x, acc[0]);
        FMA2(acc[1],  hd, w0.y, acc[1]);
        FMA2(acc[2],  hd, w1.x, acc[2]);
        FMA2(acc[3],  hd, w1.y, acc[3]);
        FMA2(acc[4],  hd, w2.x, acc[4]);
        FMA2(acc[5],  hd, w2.y, acc[5]);
        ulonglong2 w3 = wp[3], w4 = wp[4], w5 = wp[5];
        FMA2(acc[6],  hd, w3.x, acc[6]);
        FMA2(acc[7],  hd, w3.y, acc[7]);
        FMA2(acc[8],  hd, w4.x, acc[8]);
        FMA2(acc[9],  hd, w4.y, acc[9]);
        FMA2(acc[10], hd, w5.x, acc[10]);
        FMA2(acc[11], hd, w5.y, acc[11]);
        wp += 6;   // row stride = 24 floats = 6 ulonglong2
    }
    unsigned long long* rp =
        (unsigned long long*)(red + (warp * 32 + lane) * 26);
#pragma unroll
    for (int j = 0; j < 12; ++j) rp[j] = acc[j];
}

// ---------------- fused persistent pipeline ----------------
// 128 CTAs x 256 threads. CTA (bgrp, colgrp): batch [bgrp*32,+32), hidden
// cols [colgrp*8,+8). Step s: T0=layer0 rec (t=s), TX=xg1(s-1)=y0(s-1)@Wi1,
// T1=layer1 rec (t=s-2). One flat grid barrier per step.
__global__ void __launch_bounds__(256, 1) gru_fused_kernel(
    const float* __restrict__ Wh0, const float* __restrict__ bhn0,
    const float* __restrict__ Wi1, const float* __restrict__ bi1,
    const float* __restrict__ Wh1, const float* __restrict__ bhn1,
    float* __restrict__ c0out, float* __restrict__ c1out)
{
    const int NG = 24;
    extern __shared__ __align__(16) float sh[];
    float* ws0 = sh;                  // [512][24] W_h0 slice
    float* wsi = ws0 + 512 * NG;      // [512][24] W_i1 slice
    float* ws1 = wsi + 512 * NG;      // [512][24] W_h1 slice
    float* red = ws1 + 512 * NG;      // [8][32][26]
    float* xgs = red + 8 * 32 * 26;   // [32][25]

    int tid  = threadIdx.x;
    int warp = tid >> 5, lane = tid & 31;
    int cta  = blockIdx.x;
    int bgrp = cta & 1;
    int hc0  = (cta >> 1) * 8;
    int b0   = bgrp * 32;

    // load the three weight slices (once); gate col gc for slice col j
    for (int f = tid; f < 512 * NG; f += 256) {
        int k = f / NG, j = f - k * NG;
        int gc = (j >> 3) * HID + hc0 + (j & 7);
        ws0[f] = Wh0[(long)k * G3 + gc];
        wsi[f] = Wi1[(long)k * G3 + gc];
        ws1[f] = Wh1[(long)k * G3 + gc];
    }

    unsigned base = *((volatile unsigned*)&g_gen);

    int eci = tid & 7;
    int eb  = tid >> 3;
    int ehc = hc0 + eci;
    float bhn0_r = bhn0[ehc];
    float bhn1_r = bhn1[ehc];
    float bi1_r  = bi1[hc0 + eci];
    float bi1_z  = bi1[512 + hc0 + eci];
    float bi1_n  = bi1[1024 + hc0 + eci];

    // xg0 prefetch registers (warps 0-2: gate group = warp, b = lane)
    float4 xv0, xv1;
    const float* xg_base = 0;
    if (tid < 96) {
        int b = tid & 31, gg = tid >> 5;
        xg_base = g_xg + (long)(b0 + b) * G3 + gg * HID + hc0;
        xv0 = ((const float4*)xg_base)[0];   // t0 = 0
        xv1 = ((const float4*)xg_base)[1];
    }

    for (int s = 0; s < NSTEP; ++s) {
        // ======== T0: layer-0 recurrence, t0 = s ========
        if (s < TSEQ) {
            const float* hbuf = (s == 0) ? g_h0[2] : g_h0[s & 1];
            float hprev = __ldcg(&hbuf[ehc * NBATCH + b0 + eb]);

            if (tid < 96) {
                int b = tid & 31, gg = tid >> 5;
                float* q = xgs + b * 25 + gg * 8;
                q[0] = xv0.x; q[1] = xv0.y; q[2] = xv0.z; q[3] = xv0.w;
                q[4] = xv1.x; q[5] = xv1.y; q[6] = xv1.z; q[7] = xv1.w;
            }

            task_gemm(hbuf, ws0, red, warp, lane, b0);
            __syncthreads();

            float hr = 0.f, hz = 0.f, hnv = 0.f;
#pragma unroll
            for (int w = 0; w < 8; ++w) {
                const float* pr = red + (w * 32 + eb) * 26;
                hr  += pr[eci];
                hz  += pr[8 + eci];
                hnv += pr[16 + eci];
            }
            float xr = xgs[eb * 25 + eci];
            float xz = xgs[eb * 25 + 8 + eci];
            float xn = xgs[eb * 25 + 16 + eci];

            float rg = 1.f / (1.f + __expf(-(xr + hr)));
            float zg = 1.f / (1.f + __expf(-(xz + hz)));
            float ng = tanhf(xn + rg * (hnv + bhn0_r));
            float hnew = (1.f - zg) * ng + zg * hprev;

            g_h0[(s & 1) ^ 1][ehc * NBATCH + b0 + eb] = hnew;
            g_y0r[s & 1][ehc * NBATCH + b0 + eb] = tanhf(hnew);
            if (s == TSEQ - 1) c0out[(b0 + eb) * HID + ehc] = hnew;
            __syncthreads();   // red free for next task
        }

        // ======== TX: xg1(tx) = y0(tx) @ W_i1 + b_i1, tx = s-1 ========
        if (s >= 1 && s <= TSEQ) {
            const float* ybuf = g_y0r[(s - 1) & 1];
            task_gemm(ybuf, wsi, red, warp, lane, b0);
            __syncthreads();

            float xr = bi1_r, xz = bi1_z, xn = bi1_n;
#pragma unroll
            for (int w = 0; w < 8; ++w) {
                const float* pr = red + (w * 32 + eb) * 26;
                xr += pr[eci];
                xz += pr[8 + eci];
                xn += pr[16 + eci];
            }
            float* dst = g_xg1r[(s - 1) & 1] + (long)(b0 + eb) * G3;
            dst[hc0 + eci]        = xr;
            dst[512 + hc0 + eci]  = xz;
            dst[1024 + hc0 + eci] = xn;
            __syncthreads();   // red free for next task
        }

        // ======== T1: layer-1 recurrence, t1 = s-2 ========
        if (s >= 2) {
            int t1 = s - 2;
            const float* hbuf = (t1 == 0) ? g_h1[2] : g_h1[t1 & 1];
            float hprev = __ldcg(&hbuf[ehc * NBATCH + b0 + eb]);

            // xg1(t1) written at step s-1 (ring parity t1&1); load early
            const float* xsrc = g_xg1r[t1 & 1] + (long)(b0 + eb) * G3;
            float xr = __ldcg(&xsrc[hc0 + eci]);
            float xz = __ldcg(&xsrc[512 + hc0 + eci]);
            float xn = __ldcg(&xsrc[1024 + hc0 + eci]);

            task_gemm(hbuf, ws1, red, warp, lane, b0);
            __syncthreads();

            float hr = 0.f, hz = 0.f, hnv = 0.f;
#pragma unroll
            for (int w = 0; w < 8; ++w) {
                const float* pr = red + (w * 32 + eb) * 26;
                hr  += pr[eci];
                hz  += pr[8 + eci];
                hnv += pr[16 + eci];
            }
            float rg = 1.f / (1.f + __expf(-(xr + hr)));
            float zg = 1.f / (1.f + __expf(-(xz + hz)));
            float ng = tanhf(xn + rg * (hnv + bhn1_r));
            float hnew = (1.f - zg) * ng + zg * hprev;

            g_h1[(t1 & 1) ^ 1][ehc * NBATCH + b0 + eb] = hnew;
            if (t1 == TSEQ - 1) c1out[(b0 + eb) * HID + ehc] = hnew;
        }

        __syncthreads();   // all CTA writes issued before tid0's release

        unsigned target = base + (unsigned)s + 1u;

        // arrive: flat release-atomic (best measured mechanism, R8)
        if (tid == 0) {
            unsigned old;
            asm volatile("atom.release.gpu.global.add.u32 %0, [%1], %2;"
                         : "=r"(old) : "l"(&g_cnt), "r"(1u) : "memory");
            if (old == NCTA - 1u) {
                asm volatile("st.global.u32 [%0], %1;"
                             :: "l"(&g_cnt), "r"(0u) : "memory");
                asm volatile("st.release.gpu.global.u32 [%0], %1;"
                             :: "l"(&g_gen), "r"(target) : "memory");
            }
        }

        // overlap: prefetch xg0 for t0 = s+1 while the barrier completes
        if (tid < 96 && s + 1 < TSEQ) {
            const float* p = xg_base + (long)(s + 1) * NBATCH * G3;
            xv0 = ((const float4*)p)[0];
            xv1 = ((const float4*)p)[1];
        }

        // detect: tid0 acquire-polls gen, block barrier fans out
        if (tid == 0) {
            unsigned v;
            do {
                asm volatile("ld.acquire.gpu.global.u32 %0, [%1];"
                             : "=r"(v) : "l"(&g_gen));
            } while ((int)(v - target) < 0);
        }
        __syncthreads();
    }
}

// ---------------- dense head: out = tanh(tanh(c1) @ W_out + b_out) ----------------
__global__ void __launch_bounds__(512) dense_kernel(
    const float* __restrict__ Wout, const float* __restrict__ bout,
    float* __restrict__ out)
{
    __shared__ float tsh[HID];
    int b = blockIdx.x;
    int j = threadIdx.x;
    tsh[j] = tanhf(g_h1[0][j * NBATCH + b]);   // final h1 (k-major, buf 0)
    __syncthreads();
    float s = bout[j];
#pragma unroll 8
    for (int k = 0; k < HID; ++k)
        s = fmaf(tsh[k], Wout[(long)k * 512 + j], s);
    out[b * 512 + j] = tanhf(s);
}

// ---------------- launch ----------------
extern "C" void kernel_launch(void* const* d_in, const int* in_sizes, int n_in,
                              void* d_out, int out_size)
{
    const float* x     = (const float*)d_in[0];
    const float* W_i0  = (const float*)d_in[1];
    const float* b_i0  = (const float*)d_in[2];
    const float* W_h0  = (const float*)d_in[3];
    const float* b_hn0 = (const float*)d_in[4];
    const float* W_i1  = (const float*)d_in[5];
    const float* b_i1  = (const float*)d_in[6];
    const float* W_h1  = (const float*)d_in[7];
    const float* b_hn1 = (const float*)d_in[8];
    const float* W_out = (const float*)d_in[9];
    const float* b_out = (const float*)d_in[10];

    float* out = (float*)d_out;
    float* c0  = out + 64 * 512;
    float* c1  = out + 2 * 64 * 512;

    size_t fused_smem = (size_t)(3 * 512 * 24 + 8 * 32 * 26 + 32 * 25) * sizeof(float);
    cudaFuncSetAttribute(gru_fused_kernel,
                         cudaFuncAttributeMaxDynamicSharedMemorySize, (int)fused_smem);

    dim3 pgrid(G3 / 64, MROWS / 128);

    // layer-0 input projection (bulk)
    proj_kernel<<<pgrid, 256>>>(x, W_i0, b_i0, INFEAT, (long)1024 * 256, (long)256);
    // fused: rec0 + proj1 + rec1, one barrier per step
    gru_fused_kernel<<<NCTA, 256, fused_smem>>>(W_h0, b_hn0, W_i1, b_i1,
                                                W_h1, b_hn1, c0, c1);
    // head
    dense_kernel<<<64, 512>>>(W_out, b_out, out);
}

// round 12
// speedup vs baseline: 1.1395x; 1.0072x over previous
#include <cuda_runtime.h>
#include <math.h>

#define TSEQ   1024
#define NSTEP  (TSEQ + 2)
#define NBATCH 64
#define HID    512
#define G3     1536
#define INFEAT 256
#define MROWS  (TSEQ * NBATCH)   // 65536
#define NCTA   128

// packed f32x2 FMA
#define FMA2(d, a, b, c) \
    asm("fma.rn.f32x2 %0, %1, %2, %3;" : "=l"(d) : "l"(a), "l"(b), "l"(c))

__device__ __forceinline__ float2 u2f2(unsigned long long u) {
    float2 f;
    asm("mov.b64 {%0, %1}, %2;" : "=f"(f.x), "=f"(f.y) : "l"(u));
    return f;
}

// ---------------- scratch (device globals; no allocation) ----------------
__device__ float g_xg[(size_t)MROWS * G3];    // layer0 gate preacts (proj0)
__device__ float g_h0[3][HID * NBATCH];       // layer0 h ring (k-major); [2]=zero
__device__ float g_h1[3][HID * NBATCH];       // layer1 h ring; [2]=zero
__device__ float g_y0r[2][HID * NBATCH];      // y0 ring (k-major)
__device__ float g_xg1r[2][G3 * NBATCH];      // xg1 ring, col-major [gatecol][b]
__device__ unsigned g_cnt;                    // barrier count (returns to 0)
__device__ unsigned g_gen;                    // generation (monotonic)

// ---------------- input projection GEMM (layer 0 only) ----------------
__global__ void __launch_bounds__(256) proj_kernel(
    const float* __restrict__ A, const float* __restrict__ W,
    const float* __restrict__ bias, int K, long sB, long sT)
{
    const int N = G3;
    __shared__ __align__(16) float As2[16][260];
    __shared__ __align__(16) float Bs[16][64];

    int tid  = threadIdx.x;
    int row0 = blockIdx.y * 128;
    int col0 = blockIdx.x * 64;
    int tx = tid & 15, ty = tid >> 4;

    int ar  = row0 + (tid >> 1);
    const float* arow = A + (long)(ar & 63) * sB + (long)(ar >> 6) * sT;
    int akc = (tid & 1) * 8;
    int r2  = (tid >> 1) * 2;

    int bkr = tid >> 4;
    int bc  = (tid & 15) * 4;
    const float* bptr = W + (long)bkr * N + col0 + bc;

    unsigned long long acc[8][2];
#pragma unroll
    for (int i = 0; i < 8; ++i) { acc[i][0] = 0ull; acc[i][1] = 0ull; }

    for (int k0 = 0; k0 < K; k0 += 16) {
        float4 a0 = *(const float4*)(arow + k0 + akc);
        float4 a1 = *(const float4*)(arow + k0 + akc + 4);
        float4 bb = *(const float4*)(bptr + (long)k0 * N);

        *(float2*)&As2[akc + 0][r2] = make_float2(a0.x, a0.x);
        *(float2*)&As2[akc + 1][r2] = make_float2(a0.y, a0.y);
        *(float2*)&As2[akc + 2][r2] = make_float2(a0.z, a0.z);
        *(float2*)&As2[akc + 3][r2] = make_float2(a0.w, a0.w);
        *(float2*)&As2[akc + 4][r2] = make_float2(a1.x, a1.x);
        *(float2*)&As2[akc + 5][r2] = make_float2(a1.y, a1.y);
        *(float2*)&As2[akc + 6][r2] = make_float2(a1.z, a1.z);
        *(float2*)&As2[akc + 7][r2] = make_float2(a1.w, a1.w);
        *(float4*)&Bs[bkr][bc] = bb;
        __syncthreads();

#pragma unroll
        for (int kk = 0; kk < 16; ++kk) {
            ulonglong2 b01 = *(const ulonglong2*)&Bs[kk][tx * 4];
            ulonglong2 a01 = *(const ulonglong2*)&As2[kk][ty * 16];
            ulonglong2 a23 = *(const ulonglong2*)&As2[kk][ty * 16 + 4];
            ulonglong2 a45 = *(const ulonglong2*)&As2[kk][ty * 16 + 8];
            ulonglong2 a67 = *(const ulonglong2*)&As2[kk][ty * 16 + 12];
            unsigned long long ad[8] = {a01.x, a01.y, a23.x, a23.y,
                                        a45.x, a45.y, a67.x, a67.y};
#pragma unroll
            for (int i = 0; i < 8; ++i) {
                FMA2(acc[i][0], ad[i], b01.x, acc[i][0]);
                FMA2(acc[i][1], ad[i], b01.y, acc[i][1]);
            }
        }
        __syncthreads();
    }

    float4 bia = *(const float4*)(bias + col0 + tx * 4);
#pragma unroll
    for (int i = 0; i < 8; ++i) {
        long m = row0 + ty * 8 + i;
        float2 f01 = u2f2(acc[i][0]);
        float2 f23 = u2f2(acc[i][1]);
        float4 v;
        v.x = f01.x + bia.x;
        v.y = f01.y + bia.y;
        v.z = f23.x + bia.z;
        v.w = f23.y + bia.w;
        *(float4*)(g_xg + m * G3 + col0 + tx * 4) = v;
    }
}

// ---------------- shared per-task GEMM body ----------------
// src: k-major [512][64] in global; wsl: SMEM [512][24]; red: [8][32][26]
__device__ __forceinline__ void task_gemm(
    const float* __restrict__ src, const float* __restrict__ wsl,
    float* __restrict__ red, int warp, int lane, int b0)
{
    unsigned long long acc[12];
#pragma unroll
    for (int j = 0; j < 12; ++j) acc[j] = 0ull;
    int kbase = warp << 6;
    const float* hp = src + kbase * NBATCH + b0 + lane;
    const ulonglong2* wp = (const ulonglong2*)(wsl + kbase * 24);
#pragma unroll 8
    for (int kk = 0; kk < 64; ++kk) {
        float hv = __ldcg(hp); hp += NBATCH;
        unsigned long long hd;
        asm("mov.b64 %0, {%1, %1};" : "=l"(hd) : "r"(__float_as_int(hv)));
        ulonglong2 w0 = wp[0], w1 = wp[1], w2 = wp[2];
        FMA2(acc[0],  hd, w0.x, acc[0]);
        FMA2(acc[1],  hd, w0.y, acc[1]);
        FMA2(acc[2],  hd, w1.x, acc[2]);
        FMA2(acc[3],  hd, w1.y, acc[3]);
        FMA2(acc[4],  hd, w2.x, acc[4]);
        FMA2(acc[5],  hd, w2.y, acc[5]);
        ulonglong2 w3 = wp[3], w4 = wp[4], w5 = wp[5];
        FMA2(acc[6],  hd, w3.x, acc[6]);
        FMA2(acc[7],  hd, w3.y, acc[7]);
        FMA2(acc[8],  hd, w4.x, acc[8]);
        FMA2(acc[9],  hd, w4.y, acc[9]);
        FMA2(acc[10], hd, w5.x, acc[10]);
        FMA2(acc[11], hd, w5.y, acc[11]);
        wp += 6;   // row stride = 24 floats = 6 ulonglong2
    }
    unsigned long long* rp =
        (unsigned long long*)(red + (warp * 32 + lane) * 26);
#pragma unroll
    for (int j = 0; j < 12; ++j) rp[j] = acc[j];
}

// ---------------- fused persistent pipeline ----------------
// 128 CTAs x 256 threads. CTA (bgrp, colgrp): batch [bgrp*32,+32), hidden
// cols [colgrp*8,+8). Element mapping: eb = lane (batch), eci = warp (col)
// -> every per-step global access is one 128B transaction per warp.
// Step s: T0=layer0 rec (t=s), TX=xg1(s-1)=y0(s-1)@Wi1, T1=layer1 rec (t=s-2).
__global__ void __launch_bounds__(256, 1) gru_fused_kernel(
    const float* __restrict__ Wh0, const float* __restrict__ bhn0,
    const float* __restrict__ Wi1, const float* __restrict__ bi1,
    const float* __restrict__ Wh1, const float* __restrict__ bhn1,
    float* __restrict__ c0out, float* __restrict__ c1out)
{
    const int NG = 24;
    extern __shared__ __align__(16) float sh[];
    float* ws0 = sh;                  // [512][24] W_h0 slice
    float* wsi = ws0 + 512 * NG;      // [512][24] W_i1 slice
    float* ws1 = wsi + 512 * NG;      // [512][24] W_h1 slice
    float* red = ws1 + 512 * NG;      // [8][32][26]
    float* xgs = red + 8 * 32 * 26;   // [32][25]

    int tid  = threadIdx.x;
    int warp = tid >> 5, lane = tid & 31;
    int cta  = blockIdx.x;
    int bgrp = cta & 1;
    int hc0  = (cta >> 1) * 8;
    int b0   = bgrp * 32;

    // load the three weight slices (once); gate col gc for slice col j
    for (int f = tid; f < 512 * NG; f += 256) {
        int k = f / NG, j = f - k * NG;
        int gc = (j >> 3) * HID + hc0 + (j & 7);
        ws0[f] = Wh0[(long)k * G3 + gc];
        wsi[f] = Wi1[(long)k * G3 + gc];
        ws1[f] = Wh1[(long)k * G3 + gc];
    }

    unsigned base = *((volatile unsigned*)&g_gen);

    // coalesced element mapping: warp = hidden col, lane = batch row
    int eci = warp;           // 0..7 hidden col within slice
    int eb  = lane;           // 0..31 local batch row
    int ehc = hc0 + eci;
    float bhn0_r = bhn0[ehc];
    float bhn1_r = bhn1[ehc];
    float bi1_r  = bi1[ehc];
    float bi1_z  = bi1[512 + ehc];
    float bi1_n  = bi1[1024 + ehc];

    // xg0 prefetch registers (warps 0-2: gate group = warp, b = lane)
    float4 xv0, xv1;
    const float* xg_base = 0;
    if (tid < 96) {
        int b = tid & 31, gg = tid >> 5;
        xg_base = g_xg + (long)(b0 + b) * G3 + gg * HID + hc0;
        xv0 = ((const float4*)xg_base)[0];   // t0 = 0
        xv1 = ((const float4*)xg_base)[1];
    }

    for (int s = 0; s < NSTEP; ++s) {
        // ======== T0: layer-0 recurrence, t0 = s ========
        if (s < TSEQ) {
            const float* hbuf = (s == 0) ? g_h0[2] : g_h0[s & 1];
            float hprev = __ldcg(&hbuf[ehc * NBATCH + b0 + eb]);

            if (tid < 96) {
                int b = tid & 31, gg = tid >> 5;
                float* q = xgs + b * 25 + gg * 8;
                q[0] = xv0.x; q[1] = xv0.y; q[2] = xv0.z; q[3] = xv0.w;
                q[4] = xv1.x; q[5] = xv1.y; q[6] = xv1.z; q[7] = xv1.w;
            }

            task_gemm(hbuf, ws0, red, warp, lane, b0);
            __syncthreads();

            float hr = 0.f, hz = 0.f, hnv = 0.f;
#pragma unroll
            for (int w = 0; w < 8; ++w) {
                const float* pr = red + (w * 32 + eb) * 26;
                hr  += pr[eci];
                hz  += pr[8 + eci];
                hnv += pr[16 + eci];
            }
            float xr = xgs[eb * 25 + eci];
            float xz = xgs[eb * 25 + 8 + eci];
            float xn = xgs[eb * 25 + 16 + eci];

            float rg = 1.f / (1.f + __expf(-(xr + hr)));
            float zg = 1.f / (1.f + __expf(-(xz + hz)));
            float ng = tanhf(xn + rg * (hnv + bhn0_r));
            float hnew = (1.f - zg) * ng + zg * hprev;

            g_h0[(s & 1) ^ 1][ehc * NBATCH + b0 + eb] = hnew;
            g_y0r[s & 1][ehc * NBATCH + b0 + eb] = tanhf(hnew);
            if (s == TSEQ - 1) c0out[(b0 + eb) * HID + ehc] = hnew;
            __syncthreads();   // red free for next task
        }

        // ======== TX: xg1(tx) = y0(tx) @ W_i1 + b_i1, tx = s-1 ========
        if (s >= 1 && s <= TSEQ) {
            const float* ybuf = g_y0r[(s - 1) & 1];
            task_gemm(ybuf, wsi, red, warp, lane, b0);
            __syncthreads();

            float xr = bi1_r, xz = bi1_z, xn = bi1_n;
#pragma unroll
            for (int w = 0; w < 8; ++w) {
                const float* pr = red + (w * 32 + eb) * 26;
                xr += pr[eci];
                xz += pr[8 + eci];
                xn += pr[16 + eci];
            }
            // col-major [gatecol][b]: one 128B store per warp per gate
            float* dst = g_xg1r[(s - 1) & 1];
            dst[(ehc)        * NBATCH + b0 + eb] = xr;
            dst[(512 + ehc)  * NBATCH + b0 + eb] = xz;
            dst[(1024 + ehc) * NBATCH + b0 + eb] = xn;
            __syncthreads();   // red free for next task
        }

        // ======== T1: layer-1 recurrence, t1 = s-2 ========
        if (s >= 2) {
            int t1 = s - 2;
            const float* hbuf = (t1 == 0) ? g_h1[2] : g_h1[t1 & 1];
            float hprev = __ldcg(&hbuf[ehc * NBATCH + b0 + eb]);

            // xg1(t1) written at step s-1 (ring parity t1&1); coalesced loads
            const float* xsrc = g_xg1r[t1 & 1];
            float xr = __ldcg(&xsrc[(ehc)        * NBATCH + b0 + eb]);
            float xz = __ldcg(&xsrc[(512 + ehc)  * NBATCH + b0 + eb]);
            float xn = __ldcg(&xsrc[(1024 + ehc) * NBATCH + b0 + eb]);

            task_gemm(hbuf, ws1, red, warp, lane, b0);
            __syncthreads();

            float hr = 0.f, hz = 0.f, hnv = 0.f;
#pragma unroll
            for (int w = 0; w < 8; ++w) {
                const float* pr = red + (w * 32 + eb) * 26;
                hr  += pr[eci];
                hz  += pr[8 + eci];
                hnv += pr[16 + eci];
            }
            float rg = 1.f / (1.f + __expf(-(xr + hr)));
            float zg = 1.f / (1.f + __expf(-(xz + hz)));
            float ng = tanhf(xn + rg * (hnv + bhn1_r));
            float hnew = (1.f - zg) * ng + zg * hprev;

            g_h1[(t1 & 1) ^ 1][ehc * NBATCH + b0 + eb] = hnew;
            if (t1 == TSEQ - 1) c1out[(b0 + eb) * HID + ehc] = hnew;
        }

        __syncthreads();   // all CTA writes issued before tid0's release

        unsigned target = base + (unsigned)s + 1u;

        // arrive: flat release-atomic (best measured mechanism, R8)
        if (tid == 0) {
            unsigned old;
            asm volatile("atom.release.gpu.global.add.u32 %0, [%1], %2;"
                         : "=r"(old) : "l"(&g_cnt), "r"(1u) : "memory");
            if (old == NCTA - 1u) {
                asm volatile("st.global.u32 [%0], %1;"
                             :: "l"(&g_cnt), "r"(0u) : "memory");
                asm volatile("st.release.gpu.global.u32 [%0], %1;"
                             :: "l"(&g_gen), "r"(target) : "memory");
            }
        }

        // overlap: prefetch xg0 for t0 = s+1 while the barrier completes
        if (tid < 96 && s + 1 < TSEQ) {
            const float* p = xg_base + (long)(s + 1) * NBATCH * G3;
            xv0 = ((const float4*)p)[0];
            xv1 = ((const float4*)p)[1];
        }

        // detect: tid0 acquire-polls gen, block barrier fans out
        if (tid == 0) {
            unsigned v;
            do {
                asm volatile("ld.acquire.gpu.global.u32 %0, [%1];"
                             : "=r"(v) : "l"(&g_gen));
            } while ((int)(v - target) < 0);
        }
        __syncthreads();
    }
}

// ---------------- dense head: out = tanh(tanh(c1) @ W_out + b_out) ----------------
__global__ void __launch_bounds__(512) dense_kernel(
    const float* __restrict__ Wout, const float* __restrict__ bout,
    float* __restrict__ out)
{
    __shared__ float tsh[HID];
    int b = blockIdx.x;
    int j = threadIdx.x;
    tsh[j] = tanhf(g_h1[0][j * NBATCH + b]);   // final h1 (k-major, buf 0)
    __syncthreads();
    float s = bout[j];
#pragma unroll 8
    for (int k = 0; k < HID; ++k)
        s = fmaf(tsh[k], Wout[(long)k * 512 + j], s);
    out[b * 512 + j] = tanhf(s);
}

// ---------------- launch ----------------
extern "C" void kernel_launch(void* const* d_in, const int* in_sizes, int n_in,
                              void* d_out, int out_size)
{
    const float* x     = (const float*)d_in[0];
    const float* W_i0  = (const float*)d_in[1];
    const float* b_i0  = (const float*)d_in[2];
    const float* W_h0  = (const float*)d_in[3];
    const float* b_hn0 = (const float*)d_in[4];
    const float* W_i1  = (const float*)d_in[5];
    const float* b_i1  = (const float*)d_in[6];
    const float* W_h1  = (const float*)d_in[7];
    const float* b_hn1 = (const float*)d_in[8];
    const float* W_out = (const float*)d_in[9];
    const float* b_out = (const float*)d_in[10];

    float* out = (float*)d_out;
    float* c0  = out + 64 * 512;
    float* c1  = out + 2 * 64 * 512;

    size_t fused_smem = (size_t)(3 * 512 * 24 + 8 * 32 * 26 + 32 * 25) * sizeof(float);
    cudaFuncSetAttribute(gru_fused_kernel,
                         cudaFuncAttributeMaxDynamicSharedMemorySize, (int)fused_smem);

    dim3 pgrid(G3 / 64, MROWS / 128);

    // layer-0 input projection (bulk)
    proj_kernel<<<pgrid, 256>>>(x, W_i0, b_i0, INFEAT, (long)1024 * 256, (long)256);
    // fused: rec0 + proj1 + rec1, one barrier per step
    gru_fused_kernel<<<NCTA, 256, fused_smem>>>(W_h0, b_hn0, W_i1, b_i1,
                                                W_h1, b_hn1, c0, c1);
    // head
    dense_kernel<<<64, 512>>>(W_out, b_out, out);
}

// round 13
// speedup vs baseline: 1.1467x; 1.0063x over previous
#include <cuda_runtime.h>
#include <math.h>

#define TSEQ   1024
#define NSTEP  (TSEQ + 2)
#define NBATCH 64
#define HID    512
#define G3     1536
#define INFEAT 256
#define MROWS  (TSEQ * NBATCH)   // 65536
#define NCTA   128
#define REDSZ  (8 * 32 * 26)     // one task's reduction slice (floats)

// packed f32x2 FMA
#define FMA2(d, a, b, c) \
    asm("fma.rn.f32x2 %0, %1, %2, %3;" : "=l"(d) : "l"(a), "l"(b), "l"(c))

__device__ __forceinline__ float2 u2f2(unsigned long long u) {
    float2 f;
    asm("mov.b64 {%0, %1}, %2;" : "=f"(f.x), "=f"(f.y) : "l"(u));
    return f;
}

// ---------------- scratch (device globals; no allocation) ----------------
__device__ float g_xg[(size_t)MROWS * G3];    // layer0 gate preacts (proj0)
__device__ float g_h0[3][HID * NBATCH];       // layer0 h ring (k-major); [2]=zero
__device__ float g_h1[3][HID * NBATCH];       // layer1 h ring; [2]=zero
__device__ float g_y0r[2][HID * NBATCH];      // y0 ring (k-major)
__device__ float g_xg1r[2][G3 * NBATCH];      // xg1 ring, col-major [gatecol][b]
__device__ unsigned g_cntB[2 * 32];           // per-bgrp barrier count (ret 0)
__device__ unsigned g_genB[2 * 32];           // per-bgrp generation (monotonic)

// ---------------- input projection GEMM (layer 0 only) ----------------
__global__ void __launch_bounds__(256) proj_kernel(
    const float* __restrict__ A, const float* __restrict__ W,
    const float* __restrict__ bias, int K, long sB, long sT)
{
    const int N = G3;
    __shared__ __align__(16) float As2[16][260];
    __shared__ __align__(16) float Bs[16][64];

    int tid  = threadIdx.x;
    int row0 = blockIdx.y * 128;
    int col0 = blockIdx.x * 64;
    int tx = tid & 15, ty = tid >> 4;

    int ar  = row0 + (tid >> 1);
    const float* arow = A + (long)(ar & 63) * sB + (long)(ar >> 6) * sT;
    int akc = (tid & 1) * 8;
    int r2  = (tid >> 1) * 2;

    int bkr = tid >> 4;
    int bc  = (tid & 15) * 4;
    const float* bptr = W + (long)bkr * N + col0 + bc;

    unsigned long long acc[8][2];
#pragma unroll
    for (int i = 0; i < 8; ++i) { acc[i][0] = 0ull; acc[i][1] = 0ull; }

    for (int k0 = 0; k0 < K; k0 += 16) {
        float4 a0 = *(const float4*)(arow + k0 + akc);
        float4 a1 = *(const float4*)(arow + k0 + akc + 4);
        float4 bb = *(const float4*)(bptr + (long)k0 * N);

        *(float2*)&As2[akc + 0][r2] = make_float2(a0.x, a0.x);
        *(float2*)&As2[akc + 1][r2] = make_float2(a0.y, a0.y);
        *(float2*)&As2[akc + 2][r2] = make_float2(a0.z, a0.z);
        *(float2*)&As2[akc + 3][r2] = make_float2(a0.w, a0.w);
        *(float2*)&As2[akc + 4][r2] = make_float2(a1.x, a1.x);
        *(float2*)&As2[akc + 5][r2] = make_float2(a1.y, a1.y);
        *(float2*)&As2[akc + 6][r2] = make_float2(a1.z, a1.z);
        *(float2*)&As2[akc + 7][r2] = make_float2(a1.w, a1.w);
        *(float4*)&Bs[bkr][bc] = bb;
        __syncthreads();

#pragma unroll
        for (int kk = 0; kk < 16; ++kk) {
            ulonglong2 b01 = *(const ulonglong2*)&Bs[kk][tx * 4];
            ulonglong2 a01 = *(const ulonglong2*)&As2[kk][ty * 16];
            ulonglong2 a23 = *(const ulonglong2*)&As2[kk][ty * 16 + 4];
            ulonglong2 a45 = *(const ulonglong2*)&As2[kk][ty * 16 + 8];
            ulonglong2 a67 = *(const ulonglong2*)&As2[kk][ty * 16 + 12];
            unsigned long long ad[8] = {a01.x, a01.y, a23.x, a23.y,
                                        a45.x, a45.y, a67.x, a67.y};
#pragma unroll
            for (int i = 0; i < 8; ++i) {
                FMA2(acc[i][0], ad[i], b01.x, acc[i][0]);
                FMA2(acc[i][1], ad[i], b01.y, acc[i][1]);
            }
        }
        __syncthreads();
    }

    float4 bia = *(const float4*)(bias + col0 + tx * 4);
#pragma unroll
    for (int i = 0; i < 8; ++i) {
        long m = row0 + ty * 8 + i;
        float2 f01 = u2f2(acc[i][0]);
        float2 f23 = u2f2(acc[i][1]);
        float4 v;
        v.x = f01.x + bia.x;
        v.y = f01.y + bia.y;
        v.z = f23.x + bia.z;
        v.w = f23.y + bia.w;
        *(float4*)(g_xg + m * G3 + col0 + tx * 4) = v;
    }
}

// ---------------- shared per-task GEMM body ----------------
// src: k-major [512][64] in global; wsl: SMEM [512][24]; red: [8][32][26]
__device__ __forceinline__ void task_gemm(
    const float* __restrict__ src, const float* __restrict__ wsl,
    float* __restrict__ red, int warp, int lane, int b0)
{
    unsigned long long acc[12];
#pragma unroll
    for (int j = 0; j < 12; ++j) acc[j] = 0ull;
    int kbase = warp << 6;
    const float* hp = src + kbase * NBATCH + b0 + lane;
    const ulonglong2* wp = (const ulonglong2*)(wsl + kbase * 24);
#pragma unroll 8
    for (int kk = 0; kk < 64; ++kk) {
        float hv = __ldcg(hp); hp += NBATCH;
        unsigned long long hd;
        asm("mov.b64 %0, {%1, %1};" : "=l"(hd) : "r"(__float_as_int(hv)));
        ulonglong2 w0 = wp[0], w1 = wp[1], w2 = wp[2];
        FMA2(acc[0],  hd, w0.x, acc[0]);
        FMA2(acc[1],  hd, w0.y, acc[1]);
        FMA2(acc[2],  hd, w1.x, acc[2]);
        FMA2(acc[3],  hd, w1.y, acc[3]);
        FMA2(acc[4],  hd, w2.x, acc[4]);
        FMA2(acc[5],  hd, w2.y, acc[5]);
        ulonglong2 w3 = wp[3], w4 = wp[4], w5 = wp[5];
        FMA2(acc[6],  hd, w3.x, acc[6]);
        FMA2(acc[7],  hd, w3.y, acc[7]);
        FMA2(acc[8],  hd, w4.x, acc[8]);
        FMA2(acc[9],  hd, w4.y, acc[9]);
        FMA2(acc[10], hd, w5.x, acc[10]);
        FMA2(acc[11], hd, w5.y, acc[11]);
        wp += 6;   // row stride = 24 floats = 6 ulonglong2
    }
    unsigned long long* rp =
        (unsigned long long*)(red + (warp * 32 + lane) * 26);
#pragma unroll
    for (int j = 0; j < 12; ++j) rp[j] = acc[j];
}

// ---------------- fused persistent pipeline (merged phases) ----------------
// 128 CTAs x 256 threads. CTA (bgrp, colgrp): batch [bgrp*32,+32), hidden
// cols [colgrp*8,+8). Step s: three independent tasks run as ONE GEMM phase
// (no intermediate syncs, private red slices) + ONE merged reduce/gate phase.
// Barrier: per-bgrp flat release-atomic (64 arrivals).
__global__ void __launch_bounds__(256, 1) gru_fused_kernel(
    const float* __restrict__ Wh0, const float* __restrict__ bhn0,
    const float* __restrict__ Wi1, const float* __restrict__ bi1,
    const float* __restrict__ Wh1, const float* __restrict__ bhn1,
    float* __restrict__ c0out, float* __restrict__ c1out)
{
    const int NG = 24;
    extern __shared__ __align__(16) float sh[];
    float* ws0 = sh;                  // [512][24] W_h0 slice
    float* wsi = ws0 + 512 * NG;      // [512][24] W_i1 slice
    float* ws1 = wsi + 512 * NG;      // [512][24] W_h1 slice
    float* red = ws1 + 512 * NG;      // [3][8][32][26]
    float* xgs = red + 3 * REDSZ;     // [32][25]

    int tid  = threadIdx.x;
    int warp = tid >> 5, lane = tid & 31;
    int cta  = blockIdx.x;
    int bgrp = cta & 1;
    int hc0  = (cta >> 1) * 8;
    int b0   = bgrp * 32;

    unsigned* cntp = &g_cntB[bgrp * 32];
    unsigned* genp = &g_genB[bgrp * 32];

    // load the three weight slices (once); gate col gc for slice col j
    for (int f = tid; f < 512 * NG; f += 256) {
        int k = f / NG, j = f - k * NG;
        int gc = (j >> 3) * HID + hc0 + (j & 7);
        ws0[f] = Wh0[(long)k * G3 + gc];
        wsi[f] = Wi1[(long)k * G3 + gc];
        ws1[f] = Wh1[(long)k * G3 + gc];
    }

    unsigned base = *((volatile unsigned*)genp);

    // coalesced element mapping: warp = hidden col, lane = batch row
    int eci = warp;           // 0..7 hidden col within slice
    int eb  = lane;           // 0..31 local batch row
    int ehc = hc0 + eci;
    float bhn0_r = bhn0[ehc];
    float bhn1_r = bhn1[ehc];
    float bi1_r  = bi1[ehc];
    float bi1_z  = bi1[512 + ehc];
    float bi1_n  = bi1[1024 + ehc];

    // xg0 prefetch registers (warps 0-2: gate group = warp, b = lane)
    float4 xv0, xv1;
    const float* xg_base = 0;
    if (tid < 96) {
        int b = tid & 31, gg = tid >> 5;
        xg_base = g_xg + (long)(b0 + b) * G3 + gg * HID + hc0;
        xv0 = ((const float4*)xg_base)[0];   // t0 = 0
        xv1 = ((const float4*)xg_base)[1];
    }

    for (int s = 0; s < NSTEP; ++s) {
        int t1 = s - 2;
        bool doT0 = (s < TSEQ);
        bool doTX = (s >= 1 && s <= TSEQ);
        bool doT1 = (s >= 2);

        const float* hbuf0 = (s == 0) ? g_h0[2] : g_h0[s & 1];
        const float* hbuf1 = (t1 == 0) ? g_h1[2] : g_h1[t1 & 1];

        // hoisted operand loads (latency hidden under GEMM phase)
        float hprev0 = 0.f, hprev1 = 0.f, xr1 = 0.f, xz1 = 0.f, xn1 = 0.f;
        if (doT0) hprev0 = __ldcg(&hbuf0[ehc * NBATCH + b0 + eb]);
        if (doT1) {
            hprev1 = __ldcg(&hbuf1[ehc * NBATCH + b0 + eb]);
            const float* xsrc = g_xg1r[t1 & 1];
            xr1 = __ldcg(&xsrc[(ehc)        * NBATCH + b0 + eb]);
            xz1 = __ldcg(&xsrc[(512 + ehc)  * NBATCH + b0 + eb]);
            xn1 = __ldcg(&xsrc[(1024 + ehc) * NBATCH + b0 + eb]);
        }

        // stage prefetched xg0 tile (read in gate phase, after the sync)
        if (tid < 96) {
            int b = tid & 31, gg = tid >> 5;
            float* q = xgs + b * 25 + gg * 8;
            q[0] = xv0.x; q[1] = xv0.y; q[2] = xv0.z; q[3] = xv0.w;
            q[4] = xv1.x; q[5] = xv1.y; q[6] = xv1.z; q[7] = xv1.w;
        }

        // ======== single GEMM phase: three tasks, no intermediate syncs ====
        if (doT0) task_gemm(hbuf0, ws0, red, warp, lane, b0);
        if (doTX) task_gemm(g_y0r[(s - 1) & 1], wsi, red + REDSZ, warp, lane, b0);
        if (doT1) task_gemm(hbuf1, ws1, red + 2 * REDSZ, warp, lane, b0);
        __syncthreads();

        // ======== merged reduce + gate phase ========
        if (doT0) {
            float hr = 0.f, hz = 0.f, hnv = 0.f;
#pragma unroll
            for (int w = 0; w < 8; ++w) {
                const float* pr = red + (w * 32 + eb) * 26;
                hr  += pr[eci];
                hz  += pr[8 + eci];
                hnv += pr[16 + eci];
            }
            float xr = xgs[eb * 25 + eci];
            float xz = xgs[eb * 25 + 8 + eci];
            float xn = xgs[eb * 25 + 16 + eci];

            float rg = 1.f / (1.f + __expf(-(xr + hr)));
            float zg = 1.f / (1.f + __expf(-(xz + hz)));
            float ng = tanhf(xn + rg * (hnv + bhn0_r));
            float hnew = (1.f - zg) * ng + zg * hprev0;

            g_h0[(s & 1) ^ 1][ehc * NBATCH + b0 + eb] = hnew;
            g_y0r[s & 1][ehc * NBATCH + b0 + eb] = tanhf(hnew);
            if (s == TSEQ - 1) c0out[(b0 + eb) * HID + ehc] = hnew;
        }

        if (doTX) {
            float xr = bi1_r, xz = bi1_z, xn = bi1_n;
#pragma unroll
            for (int w = 0; w < 8; ++w) {
                const float* pr = red + REDSZ + (w * 32 + eb) * 26;
                xr += pr[eci];
                xz += pr[8 + eci];
                xn += pr[16 + eci];
            }
            float* dst = g_xg1r[(s - 1) & 1];
            dst[(ehc)        * NBATCH + b0 + eb] = xr;
            dst[(512 + ehc)  * NBATCH + b0 + eb] = xz;
            dst[(1024 + ehc) * NBATCH + b0 + eb] = xn;
        }

        if (doT1) {
            float hr = 0.f, hz = 0.f, hnv = 0.f;
#pragma unroll
            for (int w = 0; w < 8; ++w) {
                const float* pr = red + 2 * REDSZ + (w * 32 + eb) * 26;
                hr  += pr[eci];
                hz  += pr[8 + eci];
                hnv += pr[16 + eci];
            }
            float rg = 1.f / (1.f + __expf(-(xr1 + hr)));
            float zg = 1.f / (1.f + __expf(-(xz1 + hz)));
            float ng = tanhf(xn1 + rg * (hnv + bhn1_r));
            float hnew = (1.f - zg) * ng + zg * hprev1;

            g_h1[(t1 & 1) ^ 1][ehc * NBATCH + b0 + eb] = hnew;
            if (t1 == TSEQ - 1) c1out[(b0 + eb) * HID + ehc] = hnew;
        }

        __syncthreads();   // all CTA writes issued before tid0's release

        unsigned target = base + (unsigned)s + 1u;

        // arrive: per-bgrp flat release-atomic (64 arrivals)
        if (tid == 0) {
            unsigned old;
            asm volatile("atom.release.gpu.global.add.u32 %0, [%1], %2;"
                         : "=r"(old) : "l"(cntp), "r"(1u) : "memory");
            if (old == 63u) {
                asm volatile("st.global.u32 [%0], %1;"
                             :: "l"(cntp), "r"(0u) : "memory");
                asm volatile("st.release.gpu.global.u32 [%0], %1;"
                             :: "l"(genp), "r"(target) : "memory");
            }
        }

        // overlap: prefetch xg0 for t0 = s+1 while the barrier completes
        if (tid < 96 && s + 1 < TSEQ) {
            const float* p = xg_base + (long)(s + 1) * NBATCH * G3;
            xv0 = ((const float4*)p)[0];
            xv1 = ((const float4*)p)[1];
        }

        // detect: tid0 acquire-polls own bgrp gen, block barrier fans out
        if (tid == 0) {
            unsigned v;
            do {
                asm volatile("ld.acquire.gpu.global.u32 %0, [%1];"
                             : "=r"(v) : "l"(genp));
            } while ((int)(v - target) < 0);
        }
        __syncthreads();
    }
}

// ---------------- dense head: out = tanh(tanh(c1) @ W_out + b_out) ----------------
__global__ void __launch_bounds__(512) dense_kernel(
    const float* __restrict__ Wout, const float* __restrict__ bout,
    float* __restrict__ out)
{
    __shared__ float tsh[HID];
    int b = blockIdx.x;
    int j = threadIdx.x;
    tsh[j] = tanhf(g_h1[0][j * NBATCH + b]);   // final h1 (k-major, buf 0)
    __syncthreads();
    float s = bout[j];
#pragma unroll 8
    for (int k = 0; k < HID; ++k)
        s = fmaf(tsh[k], Wout[(long)k * 512 + j], s);
    out[b * 512 + j] = tanhf(s);
}

// ---------------- launch ----------------
extern "C" void kernel_launch(void* const* d_in, const int* in_sizes, int n_in,
                              void* d_out, int out_size)
{
    const float* x     = (const float*)d_in[0];
    const float* W_i0  = (const float*)d_in[1];
    const float* b_i0  = (const float*)d_in[2];
    const float* W_h0  = (const float*)d_in[3];
    const float* b_hn0 = (const float*)d_in[4];
    const float* W_i1  = (const float*)d_in[5];
    const float* b_i1  = (const float*)d_in[6];
    const float* W_h1  = (const float*)d_in[7];
    const float* b_hn1 = (const float*)d_in[8];
    const float* W_out = (const float*)d_in[9];
    const float* b_out = (const float*)d_in[10];

    float* out = (float*)d_out;
    float* c0  = out + 64 * 512;
    float* c1  = out + 2 * 64 * 512;

    size_t fused_smem = (size_t)(3 * 512 * 24 + 3 * REDSZ + 32 * 25) * sizeof(float);
    cudaFuncSetAttribute(gru_fused_kernel,
                         cudaFuncAttributeMaxDynamicSharedMemorySize, (int)fused_smem);

    dim3 pgrid(G3 / 64, MROWS / 128);

    // layer-0 input projection (bulk)
    proj_kernel<<<pgrid, 256>>>(x, W_i0, b_i0, INFEAT, (long)1024 * 256, (long)256);
    // fused: rec0 + proj1 + rec1, one barrier per step, merged phases
    gru_fused_kernel<<<NCTA, 256, fused_smem>>>(W_h0, b_hn0, W_i1, b_i1,
                                                W_h1, b_hn1, c0, c1);
    // head
    dense_kernel<<<64, 512>>>(W_out, b_out, out);
}

// round 14
// speedup vs baseline: 1.2180x; 1.0622x over previous
#include <cuda_runtime.h>
#include <math.h>

#define TSEQ   1024
#define NSTEP  (TSEQ + 2)
#define NBATCH 64
#define HID    512
#define G3     1536
#define INFEAT 256
#define MROWS  (TSEQ * NBATCH)   // 65536
#define NCTA   128
#define NTH    384
#define R4     (4 * 32 * 26)     // one task's reduction slice (floats)

// packed f32x2 FMA
#define FMA2(d, a, b, c) \
    asm("fma.rn.f32x2 %0, %1, %2, %3;" : "=l"(d) : "l"(a), "l"(b), "l"(c))

__device__ __forceinline__ float2 u2f2(unsigned long long u) {
    float2 f;
    asm("mov.b64 {%0, %1}, %2;" : "=f"(f.x), "=f"(f.y) : "l"(u));
    return f;
}

// ---------------- scratch (device globals; no allocation) ----------------
__device__ float g_xg[(size_t)MROWS * G3];    // layer0 gate preacts (proj0)
__device__ float g_h0[3][HID * NBATCH];       // layer0 h ring (k-major); [2]=zero
__device__ float g_h1[3][HID * NBATCH];       // layer1 h ring; [2]=zero
__device__ float g_y0r[2][HID * NBATCH];      // y0 ring (k-major)
__device__ float g_xg1r[2][G3 * NBATCH];      // xg1 ring, col-major [gatecol][b]
__device__ unsigned g_cntB[2 * 32];           // per-bgrp barrier count (ret 0)
__device__ unsigned g_genB[2 * 32];           // per-bgrp generation (monotonic)

// ---------------- input projection GEMM (layer 0 only) ----------------
__global__ void __launch_bounds__(256) proj_kernel(
    const float* __restrict__ A, const float* __restrict__ W,
    const float* __restrict__ bias, int K, long sB, long sT)
{
    const int N = G3;
    __shared__ __align__(16) float As2[16][260];
    __shared__ __align__(16) float Bs[16][64];

    int tid  = threadIdx.x;
    int row0 = blockIdx.y * 128;
    int col0 = blockIdx.x * 64;
    int tx = tid & 15, ty = tid >> 4;

    int ar  = row0 + (tid >> 1);
    const float* arow = A + (long)(ar & 63) * sB + (long)(ar >> 6) * sT;
    int akc = (tid & 1) * 8;
    int r2  = (tid >> 1) * 2;

    int bkr = tid >> 4;
    int bc  = (tid & 15) * 4;
    const float* bptr = W + (long)bkr * N + col0 + bc;

    unsigned long long acc[8][2];
#pragma unroll
    for (int i = 0; i < 8; ++i) { acc[i][0] = 0ull; acc[i][1] = 0ull; }

    for (int k0 = 0; k0 < K; k0 += 16) {
        float4 a0 = *(const float4*)(arow + k0 + akc);
        float4 a1 = *(const float4*)(arow + k0 + akc + 4);
        float4 bb = *(const float4*)(bptr + (long)k0 * N);

        *(float2*)&As2[akc + 0][r2] = make_float2(a0.x, a0.x);
        *(float2*)&As2[akc + 1][r2] = make_float2(a0.y, a0.y);
        *(float2*)&As2[akc + 2][r2] = make_float2(a0.z, a0.z);
        *(float2*)&As2[akc + 3][r2] = make_float2(a0.w, a0.w);
        *(float2*)&As2[akc + 4][r2] = make_float2(a1.x, a1.x);
        *(float2*)&As2[akc + 5][r2] = make_float2(a1.y, a1.y);
        *(float2*)&As2[akc + 6][r2] = make_float2(a1.z, a1.z);
        *(float2*)&As2[akc + 7][r2] = make_float2(a1.w, a1.w);
        *(float4*)&Bs[bkr][bc] = bb;
        __syncthreads();

#pragma unroll
        for (int kk = 0; kk < 16; ++kk) {
            ulonglong2 b01 = *(const ulonglong2*)&Bs[kk][tx * 4];
            ulonglong2 a01 = *(const ulonglong2*)&As2[kk][ty * 16];
            ulonglong2 a23 = *(const ulonglong2*)&As2[kk][ty * 16 + 4];
            ulonglong2 a45 = *(const ulonglong2*)&As2[kk][ty * 16 + 8];
            ulonglong2 a67 = *(const ulonglong2*)&As2[kk][ty * 16 + 12];
            unsigned long long ad[8] = {a01.x, a01.y, a23.x, a23.y,
                                        a45.x, a45.y, a67.x, a67.y};
#pragma unroll
            for (int i = 0; i < 8; ++i) {
                FMA2(acc[i][0], ad[i], b01.x, acc[i][0]);
                FMA2(acc[i][1], ad[i], b01.y, acc[i][1]);
            }
        }
        __syncthreads();
    }

    float4 bia = *(const float4*)(bias + col0 + tx * 4);
#pragma unroll
    for (int i = 0; i < 8; ++i) {
        long m = row0 + ty * 8 + i;
        float2 f01 = u2f2(acc[i][0]);
        float2 f23 = u2f2(acc[i][1]);
        float4 v;
        v.x = f01.x + bia.x;
        v.y = f01.y + bia.y;
        v.z = f23.x + bia.z;
        v.w = f23.y + bia.w;
        *(float4*)(g_xg + m * G3 + col0 + tx * 4) = v;
    }
}

// ---------------- per-task GEMM body (one warp: 128 k, 24 gate cols) -------
// src: k-major [512][64] global; wsl: SMEM [512][24]; redsl: [4][32][26]
__device__ __forceinline__ void task_gemm(
    const float* __restrict__ src, const float* __restrict__ wsl,
    float* __restrict__ redsl, int wt, int lane, int b0)
{
    unsigned long long acc[12];
#pragma unroll
    for (int j = 0; j < 12; ++j) acc[j] = 0ull;
    int kbase = wt << 7;                      // 128 k per warp
    const float* hp = src + kbase * NBATCH + b0 + lane;
    const ulonglong2* wp = (const ulonglong2*)(wsl + kbase * 24);
#pragma unroll 8
    for (int kk = 0; kk < 128; ++kk) {
        float hv = __ldcg(hp); hp += NBATCH;
        unsigned long long hd;
        asm("mov.b64 %0, {%1, %1};" : "=l"(hd) : "r"(__float_as_int(hv)));
        ulonglong2 w0 = wp[0], w1 = wp[1], w2 = wp[2];
        FMA2(acc[0],  hd, w0.x, acc[0]);
        FMA2(acc[1],  hd, w0.y, acc[1]);
        FMA2(acc[2],  hd, w1.x, acc[2]);
        FMA2(acc[3],  hd, w1.y, acc[3]);
        FMA2(acc[4],  hd, w2.x, acc[4]);
        FMA2(acc[5],  hd, w2.y, acc[5]);
        ulonglong2 w3 = wp[3], w4 = wp[4], w5 = wp[5];
        FMA2(acc[6],  hd, w3.x, acc[6]);
        FMA2(acc[7],  hd, w3.y, acc[7]);
        FMA2(acc[8],  hd, w4.x, acc[8]);
        FMA2(acc[9],  hd, w4.y, acc[9]);
        FMA2(acc[10], hd, w5.x, acc[10]);
        FMA2(acc[11], hd, w5.y, acc[11]);
        wp += 6;   // row stride = 24 floats = 6 ulonglong2
    }
    unsigned long long* rp =
        (unsigned long long*)(redsl + (wt * 32 + lane) * 26);
#pragma unroll
    for (int j = 0; j < 12; ++j) rp[j] = acc[j];
}

// ---------------- fused persistent pipeline (warp-specialized tasks) -------
// 128 CTAs x 384 threads. CTA (bgrp, colgrp): batch [bgrp*32,+32), hidden
// cols [colgrp*8,+8). Warps 0-3: T0 GEMM, 4-7: TX GEMM, 8-11: T1 GEMM —
// three tasks run CONCURRENTLY (3 warps/SMSP, stalls interleave).
// Gate phase: thread groups of 128 per task, 2 elements each.
__global__ void __launch_bounds__(NTH, 1) gru_fused_kernel(
    const float* __restrict__ Wh0, const float* __restrict__ bhn0,
    const float* __restrict__ Wi1, const float* __restrict__ bi1,
    const float* __restrict__ Wh1, const float* __restrict__ bhn1,
    float* __restrict__ c0out, float* __restrict__ c1out)
{
    const int NG = 24;
    extern __shared__ __align__(16) float sh[];
    float* ws0 = sh;                  // [512][24] W_h0 slice
    float* wsi = ws0 + 512 * NG;      // [512][24] W_i1 slice
    float* ws1 = wsi + 512 * NG;      // [512][24] W_h1 slice
    float* red = ws1 + 512 * NG;      // [3][4][32][26]
    float* xgs = red + 3 * R4;        // [32][25]

    int tid  = threadIdx.x;
    int warp = tid >> 5, lane = tid & 31;
    int task = warp >> 2;             // 0..2 GEMM task
    int wt   = warp & 3;              // warp within task
    int cta  = blockIdx.x;
    int bgrp = cta & 1;
    int hc0  = (cta >> 1) * 8;
    int b0   = bgrp * 32;

    unsigned* cntp = &g_cntB[bgrp * 32];
    unsigned* genp = &g_genB[bgrp * 32];

    // load the three weight slices (once); gate col gc for slice col j
    for (int f = tid; f < 512 * NG; f += NTH) {
        int k = f / NG, j = f - k * NG;
        int gc = (j >> 3) * HID + hc0 + (j & 7);
        ws0[f] = Wh0[(long)k * G3 + gc];
        wsi[f] = Wi1[(long)k * G3 + gc];
        ws1[f] = Wh1[(long)k * G3 + gc];
    }

    unsigned base = *((volatile unsigned*)genp);

    // gate-phase mapping: group gt of 128 threads handles task gt,
    // 2 elements per thread: (eb, ec0) and (eb, ec1)
    int gt  = tid / 128;              // 0..2
    int gi  = tid - gt * 128;         // 0..127
    int eb  = gi & 31;
    int ec0 = gi >> 5;                // 0..3
    int ec1 = ec0 + 4;                // 4..7
    int ehc0 = hc0 + ec0, ehc1 = hc0 + ec1;

    float cA0 = 0.f, cA1 = 0.f, cB0 = 0.f, cB1 = 0.f, cC0 = 0.f, cC1 = 0.f;
    if (gt == 0) { cA0 = bhn0[ehc0]; cA1 = bhn0[ehc1]; }
    if (gt == 1) {
        cA0 = bi1[ehc0];        cA1 = bi1[ehc1];
        cB0 = bi1[512 + ehc0];  cB1 = bi1[512 + ehc1];
        cC0 = bi1[1024 + ehc0]; cC1 = bi1[1024 + ehc1];
    }
    if (gt == 2) { cA0 = bhn1[ehc0]; cA1 = bhn1[ehc1]; }

    // xg0 prefetch registers (warps 0-2: gate group = warp, b = lane)
    float4 xv0, xv1;
    const float* xg_base = 0;
    if (tid < 96) {
        int b = tid & 31, gg = tid >> 5;
        xg_base = g_xg + (long)(b0 + b) * G3 + gg * HID + hc0;
        xv0 = ((const float4*)xg_base)[0];   // t0 = 0
        xv1 = ((const float4*)xg_base)[1];
    }

    for (int s = 0; s < NSTEP; ++s) {
        int t1 = s - 2;
        bool doT0 = (s < TSEQ);
        bool doTX = (s >= 1 && s <= TSEQ);
        bool doT1 = (s >= 2);

        const float* hbuf0 = (s == 0) ? g_h0[2] : g_h0[s & 1];
        const float* hbuf1 = (t1 == 0) ? g_h1[2] : g_h1[t1 & 1];

        // hoisted gate-operand loads (latency hidden under GEMM phase)
        float hp00 = 0.f, hp01 = 0.f, hp10 = 0.f, hp11 = 0.f;
        float xr10 = 0.f, xz10 = 0.f, xn10 = 0.f;
        float xr11 = 0.f, xz11 = 0.f, xn11 = 0.f;
        if (gt == 0 && doT0) {
            hp00 = __ldcg(&hbuf0[ehc0 * NBATCH + b0 + eb]);
            hp01 = __ldcg(&hbuf0[ehc1 * NBATCH + b0 + eb]);
        }
        if (gt == 2 && doT1) {
            hp10 = __ldcg(&hbuf1[ehc0 * NBATCH + b0 + eb]);
            hp11 = __ldcg(&hbuf1[ehc1 * NBATCH + b0 + eb]);
            const float* xsrc = g_xg1r[t1 & 1];
            xr10 = __ldcg(&xsrc[(ehc0)        * NBATCH + b0 + eb]);
            xz10 = __ldcg(&xsrc[(512 + ehc0)  * NBATCH + b0 + eb]);
            xn10 = __ldcg(&xsrc[(1024 + ehc0) * NBATCH + b0 + eb]);
            xr11 = __ldcg(&xsrc[(ehc1)        * NBATCH + b0 + eb]);
            xz11 = __ldcg(&xsrc[(512 + ehc1)  * NBATCH + b0 + eb]);
            xn11 = __ldcg(&xsrc[(1024 + ehc1) * NBATCH + b0 + eb]);
        }

        // stage prefetched xg0 tile (read in gate phase, after the sync)
        if (tid < 96) {
            int b = tid & 31, gg = tid >> 5;
            float* q = xgs + b * 25 + gg * 8;
            q[0] = xv0.x; q[1] = xv0.y; q[2] = xv0.z; q[3] = xv0.w;
            q[4] = xv1.x; q[5] = xv1.y; q[6] = xv1.z; q[7] = xv1.w;
        }

        // ======== GEMM phase: three tasks on disjoint warp groups ========
        if (task == 0) { if (doT0) task_gemm(hbuf0, ws0, red,          wt, lane, b0); }
        else if (task == 1) { if (doTX) task_gemm(g_y0r[(s - 1) & 1], wsi, red + R4, wt, lane, b0); }
        else { if (doT1) task_gemm(hbuf1, ws1, red + 2 * R4, wt, lane, b0); }
        __syncthreads();

        // ======== gate phase: group gt handles task gt, 2 elems ========
        if (gt == 0 && doT0) {
            float hr0 = 0.f, hz0 = 0.f, hn0 = 0.f;
            float hr1 = 0.f, hz1 = 0.f, hn1 = 0.f;
#pragma unroll
            for (int w = 0; w < 4; ++w) {
                const float* pr = red + (w * 32 + eb) * 26;
                hr0 += pr[ec0];      hr1 += pr[ec1];
                hz0 += pr[8 + ec0];  hz1 += pr[8 + ec1];
                hn0 += pr[16 + ec0]; hn1 += pr[16 + ec1];
            }
            float xr0 = xgs[eb * 25 + ec0],      xr1v = xgs[eb * 25 + ec1];
            float xz0 = xgs[eb * 25 + 8 + ec0],  xz1v = xgs[eb * 25 + 8 + ec1];
            float xn0 = xgs[eb * 25 + 16 + ec0], xn1v = xgs[eb * 25 + 16 + ec1];

            float rg0 = 1.f / (1.f + __expf(-(xr0 + hr0)));
            float zg0 = 1.f / (1.f + __expf(-(xz0 + hz0)));
            float ng0 = tanhf(xn0 + rg0 * (hn0 + cA0));
            float hnew0 = (1.f - zg0) * ng0 + zg0 * hp00;
            float rg1 = 1.f / (1.f + __expf(-(xr1v + hr1)));
            float zg1 = 1.f / (1.f + __expf(-(xz1v + hz1)));
            float ng1 = tanhf(xn1v + rg1 * (hn1 + cA1));
            float hnew1 = (1.f - zg1) * ng1 + zg1 * hp01;

            int nb = (s & 1) ^ 1;
            g_h0[nb][ehc0 * NBATCH + b0 + eb] = hnew0;
            g_h0[nb][ehc1 * NBATCH + b0 + eb] = hnew1;
            g_y0r[s & 1][ehc0 * NBATCH + b0 + eb] = tanhf(hnew0);
            g_y0r[s & 1][ehc1 * NBATCH + b0 + eb] = tanhf(hnew1);
            if (s == TSEQ - 1) {
                c0out[(b0 + eb) * HID + ehc0] = hnew0;
                c0out[(b0 + eb) * HID + ehc1] = hnew1;
            }
        }

        if (gt == 1 && doTX) {
            float xr0 = cA0, xz0 = cB0, xn0 = cC0;
            float xr1v = cA1, xz1v = cB1, xn1v = cC1;
#pragma unroll
            for (int w = 0; w < 4; ++w) {
                const float* pr = red + R4 + (w * 32 + eb) * 26;
                xr0  += pr[ec0];      xr1v += pr[ec1];
                xz0  += pr[8 + ec0];  xz1v += pr[8 + ec1];
                xn0  += pr[16 + ec0]; xn1v += pr[16 + ec1];
            }
            float* dst = g_xg1r[(s - 1) & 1];
            dst[(ehc0)        * NBATCH + b0 + eb] = xr0;
            dst[(512 + ehc0)  * NBATCH + b0 + eb] = xz0;
            dst[(1024 + ehc0) * NBATCH + b0 + eb] = xn0;
            dst[(ehc1)        * NBATCH + b0 + eb] = xr1v;
            dst[(512 + ehc1)  * NBATCH + b0 + eb] = xz1v;
            dst[(1024 + ehc1) * NBATCH + b0 + eb] = xn1v;
        }

        if (gt == 2 && doT1) {
            float hr0 = 0.f, hz0 = 0.f, hn0 = 0.f;
            float hr1 = 0.f, hz1 = 0.f, hn1 = 0.f;
#pragma unroll
            for (int w = 0; w < 4; ++w) {
                const float* pr = red + 2 * R4 + (w * 32 + eb) * 26;
                hr0 += pr[ec0];      hr1 += pr[ec1];
                hz0 += pr[8 + ec0];  hz1 += pr[8 + ec1];
                hn0 += pr[16 + ec0]; hn1 += pr[16 + ec1];
            }
            float rg0 = 1.f / (1.f + __expf(-(xr10 + hr0)));
            float zg0 = 1.f / (1.f + __expf(-(xz10 + hz0)));
            float ng0 = tanhf(xn10 + rg0 * (hn0 + cA0));
            float hnew0 = (1.f - zg0) * ng0 + zg0 * hp10;
            float rg1 = 1.f / (1.f + __expf(-(xr11 + hr1)));
            float zg1 = 1.f / (1.f + __expf(-(xz11 + hz1)));
            float ng1 = tanhf(xn11 + rg1 * (hn1 + cA1));
            float hnew1 = (1.f - zg1) * ng1 + zg1 * hp11;

            int nb = (t1 & 1) ^ 1;
            g_h1[nb][ehc0 * NBATCH + b0 + eb] = hnew0;
            g_h1[nb][ehc1 * NBATCH + b0 + eb] = hnew1;
            if (t1 == TSEQ - 1) {
                c1out[(b0 + eb) * HID + ehc0] = hnew0;
                c1out[(b0 + eb) * HID + ehc1] = hnew1;
            }
        }

        __syncthreads();   // all CTA writes issued before tid0's release

        unsigned target = base + (unsigned)s + 1u;

        // arrive: per-bgrp flat release-atomic (64 arrivals)
        if (tid == 0) {
            unsigned old;
            asm volatile("atom.release.gpu.global.add.u32 %0, [%1], %2;"
                         : "=r"(old) : "l"(cntp), "r"(1u) : "memory");
            if (old == 63u) {
                asm volatile("st.global.u32 [%0], %1;"
                             :: "l"(cntp), "r"(0u) : "memory");
                asm volatile("st.release.gpu.global.u32 [%0], %1;"
                             :: "l"(genp), "r"(target) : "memory");
            }
        }

        // overlap: prefetch xg0 for t0 = s+1 while the barrier completes
        if (tid < 96 && s + 1 < TSEQ) {
            const float* p = xg_base + (long)(s + 1) * NBATCH * G3;
            xv0 = ((const float4*)p)[0];
            xv1 = ((const float4*)p)[1];
        }

        // detect: tid0 acquire-polls own bgrp gen, block barrier fans out
        if (tid == 0) {
            unsigned v;
            do {
                asm volatile("ld.acquire.gpu.global.u32 %0, [%1];"
                             : "=r"(v) : "l"(genp));
            } while ((int)(v - target) < 0);
        }
        __syncthreads();
    }
}

// ---------------- dense head: out = tanh(tanh(c1) @ W_out + b_out) ----------------
__global__ void __launch_bounds__(512) dense_kernel(
    const float* __restrict__ Wout, const float* __restrict__ bout,
    float* __restrict__ out)
{
    __shared__ float tsh[HID];
    int b = blockIdx.x;
    int j = threadIdx.x;
    tsh[j] = tanhf(g_h1[0][j * NBATCH + b]);   // final h1 (k-major, buf 0)
    __syncthreads();
    float s = bout[j];
#pragma unroll 8
    for (int k = 0; k < HID; ++k)
        s = fmaf(tsh[k], Wout[(long)k * 512 + j], s);
    out[b * 512 + j] = tanhf(s);
}

// ---------------- launch ----------------
extern "C" void kernel_launch(void* const* d_in, const int* in_sizes, int n_in,
                              void* d_out, int out_size)
{
    const float* x     = (const float*)d_in[0];
    const float* W_i0  = (const float*)d_in[1];
    const float* b_i0  = (const float*)d_in[2];
    const float* W_h0  = (const float*)d_in[3];
    const float* b_hn0 = (const float*)d_in[4];
    const float* W_i1  = (const float*)d_in[5];
    const float* b_i1  = (const float*)d_in[6];
    const float* W_h1  = (const float*)d_in[7];
    const float* b_hn1 = (const float*)d_in[8];
    const float* W_out = (const float*)d_in[9];
    const float* b_out = (const float*)d_in[10];

    float* out = (float*)d_out;
    float* c0  = out + 64 * 512;
    float* c1  = out + 2 * 64 * 512;

    size_t fused_smem = (size_t)(3 * 512 * 24 + 3 * R4 + 32 * 25) * sizeof(float);
    cudaFuncSetAttribute(gru_fused_kernel,
                         cudaFuncAttributeMaxDynamicSharedMemorySize, (int)fused_smem);

    dim3 pgrid(G3 / 64, MROWS / 128);

    // layer-0 input projection (bulk)
    proj_kernel<<<pgrid, 256>>>(x, W_i0, b_i0, INFEAT, (long)1024 * 256, (long)256);
    // fused: rec0 + proj1 + rec1, warp-specialized tasks, one barrier/step
    gru_fused_kernel<<<NCTA, NTH, fused_smem>>>(W_h0, b_hn0, W_i1, b_i1,
                                                W_h1, b_hn1, c0, c1);
    // head
    dense_kernel<<<64, 512>>>(W_out, b_out, out);
}